// round 16
// baseline (speedup 1.0000x reference)
#include <cuda_runtime.h>
#include <cuda_fp16.h>
#include <cstdint>

// Problem constants
#define BATCH   2
#define SEQ     2048
#define NH      16
#define DH      64
#define DEMB    1024
#define NTOK    (BATCH*SEQ)      // 4096
#define QKV_N   (3*DEMB)         // 3072

// Scratch (device globals — no allocation inside kernel_launch)
__device__ __half g_qh[(size_t)BATCH*NH*SEQ*DH];
__device__ __half g_kh[(size_t)BATCH*NH*SEQ*DH];
__device__ __half g_vh[(size_t)BATCH*NH*SEQ*DH];
__device__ __half g_a [(size_t)NTOK*DEMB];
__device__ __half g_xh[(size_t)NTOK*DEMB];
__device__ __half g_wih[(size_t)QKV_N*DEMB];
__device__ __half g_woh[(size_t)DEMB*DEMB];

// ---------------------------------------------------------------------------
// Helpers
// ---------------------------------------------------------------------------
__device__ __forceinline__ uint32_t smem_u32(const void* p) {
    uint32_t a;
    asm("{ .reg .u64 t; cvta.to.shared.u64 t, %1; cvt.u32.u64 %0, t; }"
        : "=r"(a) : "l"(p));
    return a;
}
__device__ __forceinline__ void cp_async16(uint32_t dst, const void* src) {
    asm volatile("cp.async.cg.shared.global [%0], [%1], 16;\n" :: "r"(dst), "l"(src));
}
#define CP_COMMIT()  asm volatile("cp.async.commit_group;\n" ::: "memory")
#define CP_WAIT0()   asm volatile("cp.async.wait_group 0;\n" ::: "memory")
#define CP_WAIT1()   asm volatile("cp.async.wait_group 1;\n" ::: "memory")

#define SWZ128(off)  ((off) ^ (((off) >> 3) & 0x70))

__device__ __forceinline__ void ldmat4(uint32_t* r, uint32_t addr) {
    asm volatile("ldmatrix.sync.aligned.m8n8.x4.shared.b16 {%0,%1,%2,%3}, [%4];"
        : "=r"(r[0]), "=r"(r[1]), "=r"(r[2]), "=r"(r[3]) : "r"(addr));
}
__device__ __forceinline__ void mma_f16(float* d, const uint32_t* a, const uint32_t* b) {
    asm volatile(
        "mma.sync.aligned.m16n8k16.row.col.f32.f16.f16.f32 "
        "{%0,%1,%2,%3}, {%4,%5,%6,%7}, {%8,%9}, {%0,%1,%2,%3};"
        : "+f"(d[0]), "+f"(d[1]), "+f"(d[2]), "+f"(d[3])
        : "r"(a[0]), "r"(a[1]), "r"(a[2]), "r"(a[3]), "r"(b[0]), "r"(b[1]));
}
__device__ __forceinline__ uint32_t pack_h2(float a, float b) {
    __half2 h = __floats2half2_rn(a, b);
    return *reinterpret_cast<uint32_t*>(&h);
}

// ---------------------------------------------------------------------------
// Prepass (single kernel): fp32 -> fp16 copies of x, w_in, w_out
// ---------------------------------------------------------------------------
#define NX4  (NTOK*DEMB/4)
#define NWI4 (QKV_N*DEMB/4)
#define NWO4 (DEMB*DEMB/4)
#define NALL4 (NX4 + NWI4 + NWO4)

__global__ __launch_bounds__(256) void round_all(
    const float* __restrict__ x, const float* __restrict__ wi,
    const float* __restrict__ wo)
{
    const int i = blockIdx.x * 256 + threadIdx.x;
    const float4* src; __half* dst; int j;
    if (i < NX4)             { src = (const float4*)x;  dst = g_xh;  j = i; }
    else if (i < NX4 + NWI4) { src = (const float4*)wi; dst = g_wih; j = i - NX4; }
    else if (i < NALL4)      { src = (const float4*)wo; dst = g_woh; j = i - NX4 - NWI4; }
    else return;
    const float4 v = src[j];
    ((__half2*)dst)[2*j]   = __floats2half2_rn(v.x, v.y);
    ((__half2*)dst)[2*j+1] = __floats2half2_rn(v.z, v.w);
}

// ---------------------------------------------------------------------------
// fp16 HMMA GEMM (proven R12, unchanged)
// ---------------------------------------------------------------------------
#define MT 128
#define NT 128
#define KC 64

#define SM_STAGE (MT*128 + NT*128)
#define SM_TOTAL (3*SM_STAGE)           // 98304

template<int ROWS>
__device__ __forceinline__ void load_tile_h(uint32_t sbase, const __half* __restrict__ g,
                                            int K, int k0, int tid) {
    #pragma unroll
    for (int t = 0; t < ROWS * 8 / 256; ++t) {
        const int c = tid + t * 256;
        const int row = c >> 3, kc = c & 7;
        const uint32_t off = row * 128 + kc * 16;
        cp_async16(sbase + SWZ128(off), g + (size_t)row * K + k0 + kc * 8);
    }
}

template<int MODE>
__global__ __launch_bounds__(256, 2)
void gemm_h(const float* __restrict__ bias, float* __restrict__ C,
            int M, int N, int K)
{
    extern __shared__ __align__(1024) char smem[];
    const uint32_t sb = smem_u32(smem);
    const int tid  = threadIdx.x;
    const int lane = tid & 31;
    const int warp = tid >> 5;
    const int wm   = (warp >> 2) * 64;
    const int wn   = (warp & 3) * 32;
    const int bm   = blockIdx.y * MT;
    const int bn   = blockIdx.x * NT;

    const __half* Abase = (MODE == 2) ? (const __half*)g_a : (const __half*)g_xh;
    const __half* Bbase = (MODE == 2) ? (const __half*)g_woh : (const __half*)g_wih;
    const __half* Ag = Abase + (size_t)bm * K;
    const __half* Bg = Bbase + (size_t)bn * K;

    float acc[4][4][4];
    #pragma unroll
    for (int i = 0; i < 4; i++)
        #pragma unroll
        for (int j = 0; j < 4; j++)
            #pragma unroll
            for (int r = 0; r < 4; r++) acc[i][j][r] = 0.f;

    const int a_row  = lane & 15;
    const int a_byte = ((lane >> 4) & 1) * 16;
    const int b_row  = (lane & 7) + (((lane >> 4) & 1) << 3);
    const int b_byte = ((lane >> 3) & 1) * 16;

    load_tile_h<MT>(sb + 0*SM_STAGE, Ag, K, 0, tid);
    load_tile_h<NT>(sb + 0*SM_STAGE + MT*128, Bg, K, 0, tid);
    CP_COMMIT();
    load_tile_h<MT>(sb + 1*SM_STAGE, Ag, K, KC, tid);
    load_tile_h<NT>(sb + 1*SM_STAGE + MT*128, Bg, K, KC, tid);
    CP_COMMIT();

    const int niter = K / KC;
    int stage = 0;
    for (int it = 0; it < niter; ++it) {
        if (it + 1 < niter) { CP_WAIT1(); } else { CP_WAIT0(); }
        __syncthreads();

        if (it + 2 < niter) {
            const int s2 = (stage + 2) % 3;
            load_tile_h<MT>(sb + s2*SM_STAGE, Ag, K, (it + 2) * KC, tid);
            load_tile_h<NT>(sb + s2*SM_STAGE + MT*128, Bg, K, (it + 2) * KC, tid);
            CP_COMMIT();
        }

        const uint32_t abase = sb + stage*SM_STAGE;
        const uint32_t bbase = abase + MT*128;

        #pragma unroll
        for (int kk = 0; kk < KC / 16; ++kk) {
            uint32_t af[4][4], bf[4][2];
            #pragma unroll
            for (int mt = 0; mt < 4; ++mt) {
                const uint32_t off = (wm + mt * 16 + a_row) * 128 + kk * 32 + a_byte;
                ldmat4(af[mt], abase + SWZ128(off));
            }
            #pragma unroll
            for (int np = 0; np < 2; ++np) {
                const uint32_t off = (wn + np * 16 + b_row) * 128 + kk * 32 + b_byte;
                uint32_t r[4];
                ldmat4(r, bbase + SWZ128(off));
                bf[np*2][0]   = r[0]; bf[np*2][1]   = r[1];
                bf[np*2+1][0] = r[2]; bf[np*2+1][1] = r[3];
            }
            #pragma unroll
            for (int mt = 0; mt < 4; ++mt)
                #pragma unroll
                for (int nt = 0; nt < 4; ++nt)
                    mma_f16(acc[mt][nt], af[mt], bf[nt]);
        }
        stage = (stage + 1) % 3;
    }

    const int g  = lane >> 2;
    const int qd = lane & 3;
    #pragma unroll
    for (int nt = 0; nt < 4; ++nt) {
        const int col = bn + wn + nt * 8 + qd * 2;
        const float2 bv = *(const float2*)&bias[col];
        #pragma unroll
        for (int mt = 0; mt < 4; ++mt) {
            const int row0 = bm + wm + mt * 16 + g;
            float2 v0, v1;
            v0.x = acc[mt][nt][0] + bv.x;
            v0.y = acc[mt][nt][1] + bv.y;
            v1.x = acc[mt][nt][2] + bv.x;
            v1.y = acc[mt][nt][3] + bv.y;
            if (MODE == 1) {
                const int part = col >> 10;
                const int h = (col & 1023) >> 6;
                const int d = col & 63;
                __half* dst = (part == 0) ? g_qh : (part == 1) ? g_kh : g_vh;
                const int b0i = row0 >> 11, s0 = row0 & 2047;
                const int b1i = (row0 + 8) >> 11, s1 = (row0 + 8) & 2047;
                *(__half2*)&dst[(((size_t)(b0i*NH + h))*SEQ + s0)*DH + d] =
                    __floats2half2_rn(v0.x, v0.y);
                *(__half2*)&dst[(((size_t)(b1i*NH + h))*SEQ + s1)*DH + d] =
                    __floats2half2_rn(v1.x, v1.y);
            } else {
                *(float2*)&C[(size_t)row0 * N + col] = v0;
                *(float2*)&C[(size_t)(row0 + 8) * N + col] = v1;
            }
        }
    }
}

// ---------------------------------------------------------------------------
// Flash attention (R13 proven config: 128 threads, warp tile 32x64,
// fragment-domain softmax, manual V transpose). Only change vs R13:
// __launch_bounds__(128, 3) -> 3 CTA/SM (reg cap 170, no spill expected).
// ---------------------------------------------------------------------------
#define AQ 128
#define AK 64
#define AH_Q  0         // 16384
#define AH_K0 16384     // 8192
#define AH_K1 24576     // 8192
#define AH_VT 32768     // 8192
#define AH_PH 40960     // 16384
#define AH_TOTAL 57344

__global__ __launch_bounds__(128, 3) void attn_h(const int* __restrict__ cmask)
{
    extern __shared__ __align__(1024) char smem[];
    const uint32_t sb = smem_u32(smem);

    const int tid  = threadIdx.x;
    const int lane = tid & 31;
    const int warp = tid >> 5;
    const int bh   = blockIdx.x;
    const int qt   = gridDim.y - 1 - blockIdx.y;
    const int q0   = qt * AQ;

    const bool causal = (cmask[0] != 0);

    const __half* gq  = g_qh + ((size_t)bh * SEQ + q0) * DH;
    const __half* gkb = g_kh + (size_t)bh * SEQ * DH;
    const __half* gvb = g_vh + (size_t)bh * SEQ * DH;

    const int a_row  = lane & 15;
    const int a_byte = ((lane >> 4) & 1) * 16;
    const int b_row  = (lane & 7) + (((lane >> 4) & 1) << 3);
    const int b_byte = ((lane >> 3) & 1) * 16;
    const int g  = lane >> 2;
    const int qh = lane & 3;

    #pragma unroll
    for (int i = 0; i < 8; ++i) {
        const int c = tid + i * 128;
        const int row = c >> 3, kc = c & 7;
        cp_async16(sb + AH_Q + SWZ128((uint32_t)(row * 128 + kc * 16)),
                   gq + (size_t)row * DH + kc * 8);
    }
    CP_COMMIT();

    #pragma unroll
    for (int i = 0; i < 4; ++i) {
        const int c = tid + i * 128;
        const int row = c >> 3, kc = c & 7;
        cp_async16(sb + AH_K0 + SWZ128((uint32_t)(row * 128 + kc * 16)),
                   gkb + (size_t)row * DH + kc * 8);
    }
    CP_COMMIT();

    float oa[2][8][4];
    #pragma unroll
    for (int mt = 0; mt < 2; ++mt)
        #pragma unroll
        for (int nt = 0; nt < 8; ++nt)
            #pragma unroll
            for (int c = 0; c < 4; ++c) oa[mt][nt][c] = 0.f;
    float mrow[2][2], lrow[2][2];
    #pragma unroll
    for (int mt = 0; mt < 2; ++mt) {
        mrow[mt][0] = mrow[mt][1] = -1e30f;
        lrow[mt][0] = lrow[mt][1] = 0.f;
    }

    const int ntiles = causal ? (q0 / AK + 2) : (SEQ / AK);
    const int vkey = tid & 63;
    const int vds  = tid >> 6;
    const int rw   = q0 + warp * 32;     // warp's first q-row

    for (int t = 0; t < ntiles; ++t) {
        const int k0 = t * AK;
        const uint32_t kbase = sb + ((t & 1) ? AH_K1 : AH_K0);

        uint4 vreg[4];
        #pragma unroll
        for (int i = 0; i < 4; ++i)
            vreg[i] = *(const uint4*)(gvb + (size_t)(k0 + vkey) * DH + vds * 32 + i * 8);

        CP_WAIT0();
        __syncthreads();

        if (t + 1 < ntiles) {
            const uint32_t knext = ((t & 1) ? AH_K0 : AH_K1);
            #pragma unroll
            for (int i = 0; i < 4; ++i) {
                const int c = tid + i * 128;
                const int row = c >> 3, kc = c & 7;
                cp_async16(sb + knext + SWZ128((uint32_t)(row * 128 + kc * 16)),
                           gkb + (size_t)(k0 + AK + row) * DH + kc * 8);
            }
            CP_COMMIT();
        }

        // ---- S = Q @ K^T (fp16, proven addressing) ----
        float sc[2][8][4];
        #pragma unroll
        for (int mt = 0; mt < 2; ++mt)
            #pragma unroll
            for (int nt = 0; nt < 8; ++nt)
                #pragma unroll
                for (int c = 0; c < 4; ++c) sc[mt][nt][c] = 0.f;

        #pragma unroll
        for (int kk = 0; kk < 4; ++kk) {
            uint32_t aq[2][4], bf[8][2];
            #pragma unroll
            for (int mt = 0; mt < 2; ++mt) {
                const uint32_t off = (warp*32 + mt*16 + a_row) * 128 + kk * 32 + a_byte;
                ldmat4(aq[mt], sb + AH_Q + SWZ128(off));
            }
            #pragma unroll
            for (int np = 0; np < 4; ++np) {
                const uint32_t off = (np*16 + b_row) * 128 + kk * 32 + b_byte;
                uint32_t r[4];
                ldmat4(r, kbase + SWZ128(off));
                bf[np*2][0]   = r[0]; bf[np*2][1]   = r[1];
                bf[np*2+1][0] = r[2]; bf[np*2+1][1] = r[3];
            }
            #pragma unroll
            for (int mt = 0; mt < 2; ++mt)
                #pragma unroll
                for (int nt = 0; nt < 8; ++nt)
                    mma_f16(sc[mt][nt], aq[mt], bf[nt]);
        }

        // ---- V(t) registers -> V^T half tile (proven swizzled STS) ----
        {
            #pragma unroll
            for (int i = 0; i < 4; ++i) {
                __half h[8];
                *(uint4*)h = vreg[i];
                #pragma unroll
                for (int j = 0; j < 8; ++j) {
                    const int d = vds * 32 + i * 8 + j;
                    *(__half*)(smem + AH_VT
                        + SWZ128((uint32_t)(d * 128) + (uint32_t)(vkey * 2))) = h[j];
                }
            }
        }

        // ---- scale + causal mask (fragment coords) ----
        #pragma unroll
        for (int mt = 0; mt < 2; ++mt)
            #pragma unroll
            for (int nt = 0; nt < 8; ++nt)
                #pragma unroll
                for (int c = 0; c < 4; ++c) sc[mt][nt][c] *= 0.125f;

        if (causal && (k0 + AK - 1 > rw)) {
            #pragma unroll
            for (int mt = 0; mt < 2; ++mt)
                #pragma unroll
                for (int nt = 0; nt < 8; ++nt)
                    #pragma unroll
                    for (int c = 0; c < 4; ++c) {
                        const int row = rw + mt*16 + g + (c >> 1) * 8;
                        const int col = k0 + nt*8 + 2*qh + (c & 1);
                        if (col > row) sc[mt][nt][c] = -1e30f;
                    }
        }

        // ---- online softmax, fragment domain ----
        #pragma unroll
        for (int mt = 0; mt < 2; ++mt) {
            #pragma unroll
            for (int half = 0; half < 2; ++half) {
                float tmax = -1e30f;
                #pragma unroll
                for (int nt = 0; nt < 8; ++nt)
                    tmax = fmaxf(tmax, fmaxf(sc[mt][nt][half*2], sc[mt][nt][half*2+1]));
                tmax = fmaxf(tmax, __shfl_xor_sync(0xffffffffu, tmax, 1));
                tmax = fmaxf(tmax, __shfl_xor_sync(0xffffffffu, tmax, 2));
                const float mn = fmaxf(mrow[mt][half], tmax);
                const float corr = __expf(mrow[mt][half] - mn);
                mrow[mt][half] = mn;
                float rs = 0.f;
                #pragma unroll
                for (int nt = 0; nt < 8; ++nt) {
                    const float p0 = __expf(sc[mt][nt][half*2]   - mn);
                    const float p1 = __expf(sc[mt][nt][half*2+1] - mn);
                    sc[mt][nt][half*2]   = p0;
                    sc[mt][nt][half*2+1] = p1;
                    rs += p0 + p1;
                    oa[mt][nt][half*2]   *= corr;
                    oa[mt][nt][half*2+1] *= corr;
                }
                rs += __shfl_xor_sync(0xffffffffu, rs, 1);
                rs += __shfl_xor_sync(0xffffffffu, rs, 2);
                lrow[mt][half] = lrow[mt][half] * corr + rs;
            }
        }

        // ---- P fragments -> P_H half tile (direct half2 stores) ----
        #pragma unroll
        for (int mt = 0; mt < 2; ++mt) {
            const int row0 = warp*32 + mt*16 + g;
            #pragma unroll
            for (int nt = 0; nt < 8; ++nt) {
                const uint32_t cb = (uint32_t)(nt*16 + 4*qh);
                *(uint32_t*)(smem + AH_PH + SWZ128((uint32_t)(row0 * 128) + cb)) =
                    pack_h2(sc[mt][nt][0], sc[mt][nt][1]);
                *(uint32_t*)(smem + AH_PH + SWZ128((uint32_t)((row0 + 8) * 128) + cb)) =
                    pack_h2(sc[mt][nt][2], sc[mt][nt][3]);
            }
        }

        __syncthreads();   // V^T + P_H visible

        // ---- O += P @ V (fp16, proven addressing) ----
        #pragma unroll
        for (int kk = 0; kk < 4; ++kk) {
            uint32_t ap[2][4], bf[8][2];
            #pragma unroll
            for (int mt = 0; mt < 2; ++mt) {
                const uint32_t off = (warp*32 + mt*16 + a_row) * 128 + kk * 32 + a_byte;
                ldmat4(ap[mt], sb + AH_PH + SWZ128(off));
            }
            #pragma unroll
            for (int np = 0; np < 4; ++np) {
                const uint32_t off = (np*16 + b_row) * 128 + kk * 32 + b_byte;
                uint32_t r[4];
                ldmat4(r, sb + AH_VT + SWZ128(off));
                bf[np*2][0]   = r[0]; bf[np*2][1]   = r[1];
                bf[np*2+1][0] = r[2]; bf[np*2+1][1] = r[3];
            }
            #pragma unroll
            for (int mt = 0; mt < 2; ++mt)
                #pragma unroll
                for (int nt = 0; nt < 8; ++nt)
                    mma_f16(oa[mt][nt], ap[mt], bf[nt]);
        }
    }

    // ---- normalize (lane-local l) + write g_a as HALF ----
    const int b = bh >> 4, h = bh & 15;
    #pragma unroll
    for (int mt = 0; mt < 2; ++mt) {
        const int r0 = warp*32 + mt*16 + g;
        const float i0 = 1.f / fmaxf(lrow[mt][0], 1e-30f);
        const float i1 = 1.f / fmaxf(lrow[mt][1], 1e-30f);
        __half* o0 = g_a + ((size_t)(b * SEQ + q0 + r0)) * DEMB + h * DH;
        __half* o1 = g_a + ((size_t)(b * SEQ + q0 + r0 + 8)) * DEMB + h * DH;
        #pragma unroll
        for (int nt = 0; nt < 8; ++nt) {
            *(__half2*)(o0 + nt*8 + 2*qh) =
                __floats2half2_rn(oa[mt][nt][0] * i0, oa[mt][nt][1] * i0);
            *(__half2*)(o1 + nt*8 + 2*qh) =
                __floats2half2_rn(oa[mt][nt][2] * i1, oa[mt][nt][3] * i1);
        }
    }
}

// ---------------------------------------------------------------------------
extern "C" void kernel_launch(void* const* d_in, const int* in_sizes, int n_in,
                              void* d_out, int out_size)
{
    const float* x     = (const float*)d_in[0];
    const float* w_in  = (const float*)d_in[1];
    const float* b_in  = (const float*)d_in[2];
    const float* w_out = (const float*)d_in[3];
    const float* b_out = (const float*)d_in[4];
    const int*   cmask = (const int*)d_in[5];
    float* out = (float*)d_out;

    cudaFuncSetAttribute(gemm_h<1>, cudaFuncAttributeMaxDynamicSharedMemorySize, SM_TOTAL);
    cudaFuncSetAttribute(gemm_h<2>, cudaFuncAttributeMaxDynamicSharedMemorySize, SM_TOTAL);
    cudaFuncSetAttribute(attn_h,    cudaFuncAttributeMaxDynamicSharedMemorySize, AH_TOTAL);

    round_all<<<(NALL4 + 255) / 256, 256>>>(x, w_in, w_out);

    gemm_h<1><<<dim3(QKV_N/NT, NTOK/MT), 256, SM_TOTAL>>>(
        b_in, nullptr, NTOK, QKV_N, DEMB);

    attn_h<<<dim3(BATCH*NH, SEQ/AQ), 128, AH_TOTAL>>>(cmask);

    gemm_h<2><<<dim3(DEMB/NT, NTOK/MT), 256, SM_TOTAL>>>(
        b_out, out, NTOK, DEMB, DEMB);
}

// round 17
// speedup vs baseline: 1.2461x; 1.2461x over previous
#include <cuda_runtime.h>
#include <cuda_fp16.h>
#include <cstdint>

// Problem constants
#define BATCH   2
#define SEQ     2048
#define NH      16
#define DH      64
#define DEMB    1024
#define NTOK    (BATCH*SEQ)      // 4096
#define QKV_N   (3*DEMB)         // 3072

// Scratch (device globals — no allocation inside kernel_launch)
__device__ __half g_qh[(size_t)BATCH*NH*SEQ*DH];
__device__ __half g_kh[(size_t)BATCH*NH*SEQ*DH];
__device__ __half g_vh[(size_t)BATCH*NH*SEQ*DH];
__device__ __half g_a [(size_t)NTOK*DEMB];
__device__ __half g_xh[(size_t)NTOK*DEMB];
__device__ __half g_wih[(size_t)QKV_N*DEMB];
__device__ __half g_woh[(size_t)DEMB*DEMB];

// ---------------------------------------------------------------------------
// Helpers
// ---------------------------------------------------------------------------
__device__ __forceinline__ uint32_t smem_u32(const void* p) {
    uint32_t a;
    asm("{ .reg .u64 t; cvta.to.shared.u64 t, %1; cvt.u32.u64 %0, t; }"
        : "=r"(a) : "l"(p));
    return a;
}
__device__ __forceinline__ void cp_async16(uint32_t dst, const void* src) {
    asm volatile("cp.async.cg.shared.global [%0], [%1], 16;\n" :: "r"(dst), "l"(src));
}
#define CP_COMMIT()  asm volatile("cp.async.commit_group;\n" ::: "memory")
#define CP_WAIT0()   asm volatile("cp.async.wait_group 0;\n" ::: "memory")
#define CP_WAIT1()   asm volatile("cp.async.wait_group 1;\n" ::: "memory")

#define SWZ128(off)  ((off) ^ (((off) >> 3) & 0x70))

__device__ __forceinline__ void ldmat4(uint32_t* r, uint32_t addr) {
    asm volatile("ldmatrix.sync.aligned.m8n8.x4.shared.b16 {%0,%1,%2,%3}, [%4];"
        : "=r"(r[0]), "=r"(r[1]), "=r"(r[2]), "=r"(r[3]) : "r"(addr));
}
__device__ __forceinline__ void mma_f16(float* d, const uint32_t* a, const uint32_t* b) {
    asm volatile(
        "mma.sync.aligned.m16n8k16.row.col.f32.f16.f16.f32 "
        "{%0,%1,%2,%3}, {%4,%5,%6,%7}, {%8,%9}, {%0,%1,%2,%3};"
        : "+f"(d[0]), "+f"(d[1]), "+f"(d[2]), "+f"(d[3])
        : "r"(a[0]), "r"(a[1]), "r"(a[2]), "r"(a[3]), "r"(b[0]), "r"(b[1]));
}
__device__ __forceinline__ uint32_t pack_h2(float a, float b) {
    __half2 h = __floats2half2_rn(a, b);
    return *reinterpret_cast<uint32_t*>(&h);
}

// ---------------------------------------------------------------------------
// Prepass (single kernel): fp32 -> fp16 copies of x, w_in, w_out
// ---------------------------------------------------------------------------
#define NX4  (NTOK*DEMB/4)
#define NWI4 (QKV_N*DEMB/4)
#define NWO4 (DEMB*DEMB/4)
#define NALL4 (NX4 + NWI4 + NWO4)

__global__ __launch_bounds__(256) void round_all(
    const float* __restrict__ x, const float* __restrict__ wi,
    const float* __restrict__ wo)
{
    const int i = blockIdx.x * 256 + threadIdx.x;
    const float4* src; __half* dst; int j;
    if (i < NX4)             { src = (const float4*)x;  dst = g_xh;  j = i; }
    else if (i < NX4 + NWI4) { src = (const float4*)wi; dst = g_wih; j = i - NX4; }
    else if (i < NALL4)      { src = (const float4*)wo; dst = g_woh; j = i - NX4 - NWI4; }
    else return;
    const float4 v = src[j];
    ((__half2*)dst)[2*j]   = __floats2half2_rn(v.x, v.y);
    ((__half2*)dst)[2*j+1] = __floats2half2_rn(v.z, v.w);
}

// ---------------------------------------------------------------------------
// fp16 HMMA GEMM (proven R12, unchanged)
// ---------------------------------------------------------------------------
#define MT 128
#define NT 128
#define KC 64

#define SM_STAGE (MT*128 + NT*128)
#define SM_TOTAL (3*SM_STAGE)           // 98304

template<int ROWS>
__device__ __forceinline__ void load_tile_h(uint32_t sbase, const __half* __restrict__ g,
                                            int K, int k0, int tid) {
    #pragma unroll
    for (int t = 0; t < ROWS * 8 / 256; ++t) {
        const int c = tid + t * 256;
        const int row = c >> 3, kc = c & 7;
        const uint32_t off = row * 128 + kc * 16;
        cp_async16(sbase + SWZ128(off), g + (size_t)row * K + k0 + kc * 8);
    }
}

template<int MODE>
__global__ __launch_bounds__(256, 2)
void gemm_h(const float* __restrict__ bias, float* __restrict__ C,
            int M, int N, int K)
{
    extern __shared__ __align__(1024) char smem[];
    const uint32_t sb = smem_u32(smem);
    const int tid  = threadIdx.x;
    const int lane = tid & 31;
    const int warp = tid >> 5;
    const int wm   = (warp >> 2) * 64;
    const int wn   = (warp & 3) * 32;
    const int bm   = blockIdx.y * MT;
    const int bn   = blockIdx.x * NT;

    const __half* Abase = (MODE == 2) ? (const __half*)g_a : (const __half*)g_xh;
    const __half* Bbase = (MODE == 2) ? (const __half*)g_woh : (const __half*)g_wih;
    const __half* Ag = Abase + (size_t)bm * K;
    const __half* Bg = Bbase + (size_t)bn * K;

    float acc[4][4][4];
    #pragma unroll
    for (int i = 0; i < 4; i++)
        #pragma unroll
        for (int j = 0; j < 4; j++)
            #pragma unroll
            for (int r = 0; r < 4; r++) acc[i][j][r] = 0.f;

    const int a_row  = lane & 15;
    const int a_byte = ((lane >> 4) & 1) * 16;
    const int b_row  = (lane & 7) + (((lane >> 4) & 1) << 3);
    const int b_byte = ((lane >> 3) & 1) * 16;

    load_tile_h<MT>(sb + 0*SM_STAGE, Ag, K, 0, tid);
    load_tile_h<NT>(sb + 0*SM_STAGE + MT*128, Bg, K, 0, tid);
    CP_COMMIT();
    load_tile_h<MT>(sb + 1*SM_STAGE, Ag, K, KC, tid);
    load_tile_h<NT>(sb + 1*SM_STAGE + MT*128, Bg, K, KC, tid);
    CP_COMMIT();

    const int niter = K / KC;
    int stage = 0;
    for (int it = 0; it < niter; ++it) {
        if (it + 1 < niter) { CP_WAIT1(); } else { CP_WAIT0(); }
        __syncthreads();

        if (it + 2 < niter) {
            const int s2 = (stage + 2) % 3;
            load_tile_h<MT>(sb + s2*SM_STAGE, Ag, K, (it + 2) * KC, tid);
            load_tile_h<NT>(sb + s2*SM_STAGE + MT*128, Bg, K, (it + 2) * KC, tid);
            CP_COMMIT();
        }

        const uint32_t abase = sb + stage*SM_STAGE;
        const uint32_t bbase = abase + MT*128;

        #pragma unroll
        for (int kk = 0; kk < KC / 16; ++kk) {
            uint32_t af[4][4], bf[4][2];
            #pragma unroll
            for (int mt = 0; mt < 4; ++mt) {
                const uint32_t off = (wm + mt * 16 + a_row) * 128 + kk * 32 + a_byte;
                ldmat4(af[mt], abase + SWZ128(off));
            }
            #pragma unroll
            for (int np = 0; np < 2; ++np) {
                const uint32_t off = (wn + np * 16 + b_row) * 128 + kk * 32 + b_byte;
                uint32_t r[4];
                ldmat4(r, bbase + SWZ128(off));
                bf[np*2][0]   = r[0]; bf[np*2][1]   = r[1];
                bf[np*2+1][0] = r[2]; bf[np*2+1][1] = r[3];
            }
            #pragma unroll
            for (int mt = 0; mt < 4; ++mt)
                #pragma unroll
                for (int nt = 0; nt < 4; ++nt)
                    mma_f16(acc[mt][nt], af[mt], bf[nt]);
        }
        stage = (stage + 1) % 3;
    }

    const int g  = lane >> 2;
    const int qd = lane & 3;
    #pragma unroll
    for (int nt = 0; nt < 4; ++nt) {
        const int col = bn + wn + nt * 8 + qd * 2;
        const float2 bv = *(const float2*)&bias[col];
        #pragma unroll
        for (int mt = 0; mt < 4; ++mt) {
            const int row0 = bm + wm + mt * 16 + g;
            float2 v0, v1;
            v0.x = acc[mt][nt][0] + bv.x;
            v0.y = acc[mt][nt][1] + bv.y;
            v1.x = acc[mt][nt][2] + bv.x;
            v1.y = acc[mt][nt][3] + bv.y;
            if (MODE == 1) {
                const int part = col >> 10;
                const int h = (col & 1023) >> 6;
                const int d = col & 63;
                __half* dst = (part == 0) ? g_qh : (part == 1) ? g_kh : g_vh;
                const int b0i = row0 >> 11, s0 = row0 & 2047;
                const int b1i = (row0 + 8) >> 11, s1 = (row0 + 8) & 2047;
                *(__half2*)&dst[(((size_t)(b0i*NH + h))*SEQ + s0)*DH + d] =
                    __floats2half2_rn(v0.x, v0.y);
                *(__half2*)&dst[(((size_t)(b1i*NH + h))*SEQ + s1)*DH + d] =
                    __floats2half2_rn(v1.x, v1.y);
            } else {
                *(float2*)&C[(size_t)row0 * N + col] = v0;
                *(float2*)&C[(size_t)(row0 + 8) * N + col] = v1;
            }
        }
    }
}

// ---------------------------------------------------------------------------
// Flash attention (R13 proven config: 128 threads, 2 CTA/SM, warp tile
// 32x64, fragment softmax, manual V transpose) with three cuts:
//  1) Q fragments hoisted out of the k-tile loop (loaded once)
//  2) exp2-domain softmax (log2e folded into scale)
//  3) fully-masked warp-tiles skipped (exactly equivalent work)
// ---------------------------------------------------------------------------
#define AQ 128
#define AK 64
#define AH_Q  0         // 16384
#define AH_K0 16384     // 8192
#define AH_K1 24576     // 8192
#define AH_VT 32768     // 8192
#define AH_PH 40960     // 16384
#define AH_TOTAL 57344

#define SCL2E 0.1803368801111204f   // 0.125 * log2(e)

__global__ __launch_bounds__(128, 2) void attn_h(const int* __restrict__ cmask)
{
    extern __shared__ __align__(1024) char smem[];
    const uint32_t sb = smem_u32(smem);

    const int tid  = threadIdx.x;
    const int lane = tid & 31;
    const int warp = tid >> 5;
    const int bh   = blockIdx.x;
    const int qt   = gridDim.y - 1 - blockIdx.y;
    const int q0   = qt * AQ;

    const bool causal = (cmask[0] != 0);

    const __half* gq  = g_qh + ((size_t)bh * SEQ + q0) * DH;
    const __half* gkb = g_kh + (size_t)bh * SEQ * DH;
    const __half* gvb = g_vh + (size_t)bh * SEQ * DH;

    const int a_row  = lane & 15;
    const int a_byte = ((lane >> 4) & 1) * 16;
    const int b_row  = (lane & 7) + (((lane >> 4) & 1) << 3);
    const int b_byte = ((lane >> 3) & 1) * 16;
    const int g  = lane >> 2;
    const int qh = lane & 3;

    // ---- Q tile (cp.async, group A) ----
    #pragma unroll
    for (int i = 0; i < 8; ++i) {
        const int c = tid + i * 128;
        const int row = c >> 3, kc = c & 7;
        cp_async16(sb + AH_Q + SWZ128((uint32_t)(row * 128 + kc * 16)),
                   gq + (size_t)row * DH + kc * 8);
    }
    CP_COMMIT();

    // ---- K(0) tile (cp.async, group B) ----
    #pragma unroll
    for (int i = 0; i < 4; ++i) {
        const int c = tid + i * 128;
        const int row = c >> 3, kc = c & 7;
        cp_async16(sb + AH_K0 + SWZ128((uint32_t)(row * 128 + kc * 16)),
                   gkb + (size_t)row * DH + kc * 8);
    }
    CP_COMMIT();

    // ---- hoist Q fragments (tile-invariant) ----
    CP_WAIT1();          // Q group done; K(0) may still be in flight
    __syncthreads();
    uint32_t aqf[4][2][4];
    #pragma unroll
    for (int kk = 0; kk < 4; ++kk)
        #pragma unroll
        for (int mt = 0; mt < 2; ++mt) {
            const uint32_t off = (warp*32 + mt*16 + a_row) * 128 + kk * 32 + a_byte;
            ldmat4(aqf[kk][mt], sb + AH_Q + SWZ128(off));
        }

    float oa[2][8][4];
    #pragma unroll
    for (int mt = 0; mt < 2; ++mt)
        #pragma unroll
        for (int nt = 0; nt < 8; ++nt)
            #pragma unroll
            for (int c = 0; c < 4; ++c) oa[mt][nt][c] = 0.f;
    float mrow[2][2], lrow[2][2];
    #pragma unroll
    for (int mt = 0; mt < 2; ++mt) {
        mrow[mt][0] = mrow[mt][1] = -1e30f;
        lrow[mt][0] = lrow[mt][1] = 0.f;
    }

    const int ntiles = causal ? (q0 / AK + 2) : (SEQ / AK);
    const int vkey = tid & 63;
    const int vds  = tid >> 6;
    const int rw   = q0 + warp * 32;     // warp's first q-row

    for (int t = 0; t < ntiles; ++t) {
        const int k0 = t * AK;
        const uint32_t kbase = sb + ((t & 1) ? AH_K1 : AH_K0);
        // fully-masked warp-tile? (all cols > all rows) -> skip compute
        const bool wactive = !causal || (k0 <= rw + 31);

        uint4 vreg[4];
        #pragma unroll
        for (int i = 0; i < 4; ++i)
            vreg[i] = *(const uint4*)(gvb + (size_t)(k0 + vkey) * DH + vds * 32 + i * 8);

        CP_WAIT0();
        __syncthreads();

        if (t + 1 < ntiles) {
            const uint32_t knext = ((t & 1) ? AH_K0 : AH_K1);
            #pragma unroll
            for (int i = 0; i < 4; ++i) {
                const int c = tid + i * 128;
                const int row = c >> 3, kc = c & 7;
                cp_async16(sb + knext + SWZ128((uint32_t)(row * 128 + kc * 16)),
                           gkb + (size_t)(k0 + AK + row) * DH + kc * 8);
            }
            CP_COMMIT();
        }

        float sc[2][8][4];
        if (wactive) {
            // ---- S = Q @ K^T (Q fragments from registers) ----
            #pragma unroll
            for (int mt = 0; mt < 2; ++mt)
                #pragma unroll
                for (int nt = 0; nt < 8; ++nt)
                    #pragma unroll
                    for (int c = 0; c < 4; ++c) sc[mt][nt][c] = 0.f;

            #pragma unroll
            for (int kk = 0; kk < 4; ++kk) {
                uint32_t bf[8][2];
                #pragma unroll
                for (int np = 0; np < 4; ++np) {
                    const uint32_t off = (np*16 + b_row) * 128 + kk * 32 + b_byte;
                    uint32_t r[4];
                    ldmat4(r, kbase + SWZ128(off));
                    bf[np*2][0]   = r[0]; bf[np*2][1]   = r[1];
                    bf[np*2+1][0] = r[2]; bf[np*2+1][1] = r[3];
                }
                #pragma unroll
                for (int mt = 0; mt < 2; ++mt)
                    #pragma unroll
                    for (int nt = 0; nt < 8; ++nt)
                        mma_f16(sc[mt][nt], aqf[kk][mt], bf[nt]);
            }
        }

        // ---- V(t) registers -> V^T half tile (all threads) ----
        {
            #pragma unroll
            for (int i = 0; i < 4; ++i) {
                __half h[8];
                *(uint4*)h = vreg[i];
                #pragma unroll
                for (int j = 0; j < 8; ++j) {
                    const int d = vds * 32 + i * 8 + j;
                    *(__half*)(smem + AH_VT
                        + SWZ128((uint32_t)(d * 128) + (uint32_t)(vkey * 2))) = h[j];
                }
            }
        }

        if (wactive) {
            // ---- scale (log2 domain) + causal mask ----
            #pragma unroll
            for (int mt = 0; mt < 2; ++mt)
                #pragma unroll
                for (int nt = 0; nt < 8; ++nt)
                    #pragma unroll
                    for (int c = 0; c < 4; ++c) sc[mt][nt][c] *= SCL2E;

            if (causal && (k0 + AK - 1 > rw)) {
                #pragma unroll
                for (int mt = 0; mt < 2; ++mt)
                    #pragma unroll
                    for (int nt = 0; nt < 8; ++nt)
                        #pragma unroll
                        for (int c = 0; c < 4; ++c) {
                            const int row = rw + mt*16 + g + (c >> 1) * 8;
                            const int col = k0 + nt*8 + 2*qh + (c & 1);
                            if (col > row) sc[mt][nt][c] = -1e30f;
                        }
            }

            // ---- online softmax (exp2 domain) ----
            #pragma unroll
            for (int mt = 0; mt < 2; ++mt) {
                #pragma unroll
                for (int half = 0; half < 2; ++half) {
                    float tmax = -1e30f;
                    #pragma unroll
                    for (int nt = 0; nt < 8; ++nt)
                        tmax = fmaxf(tmax, fmaxf(sc[mt][nt][half*2], sc[mt][nt][half*2+1]));
                    tmax = fmaxf(tmax, __shfl_xor_sync(0xffffffffu, tmax, 1));
                    tmax = fmaxf(tmax, __shfl_xor_sync(0xffffffffu, tmax, 2));
                    const float mn = fmaxf(mrow[mt][half], tmax);
                    const float corr = exp2f(mrow[mt][half] - mn);
                    mrow[mt][half] = mn;
                    float rs = 0.f;
                    #pragma unroll
                    for (int nt = 0; nt < 8; ++nt) {
                        const float p0 = exp2f(sc[mt][nt][half*2]   - mn);
                        const float p1 = exp2f(sc[mt][nt][half*2+1] - mn);
                        sc[mt][nt][half*2]   = p0;
                        sc[mt][nt][half*2+1] = p1;
                        rs += p0 + p1;
                        oa[mt][nt][half*2]   *= corr;
                        oa[mt][nt][half*2+1] *= corr;
                    }
                    rs += __shfl_xor_sync(0xffffffffu, rs, 1);
                    rs += __shfl_xor_sync(0xffffffffu, rs, 2);
                    lrow[mt][half] = lrow[mt][half] * corr + rs;
                }
            }

            // ---- P fragments -> P_H half tile ----
            #pragma unroll
            for (int mt = 0; mt < 2; ++mt) {
                const int row0 = warp*32 + mt*16 + g;
                #pragma unroll
                for (int nt = 0; nt < 8; ++nt) {
                    const uint32_t cb = (uint32_t)(nt*16 + 4*qh);
                    *(uint32_t*)(smem + AH_PH + SWZ128((uint32_t)(row0 * 128) + cb)) =
                        pack_h2(sc[mt][nt][0], sc[mt][nt][1]);
                    *(uint32_t*)(smem + AH_PH + SWZ128((uint32_t)((row0 + 8) * 128) + cb)) =
                        pack_h2(sc[mt][nt][2], sc[mt][nt][3]);
                }
            }
        }

        __syncthreads();   // V^T + P_H visible

        if (wactive) {
            // ---- O += P @ V (fp16, proven addressing) ----
            #pragma unroll
            for (int kk = 0; kk < 4; ++kk) {
                uint32_t ap[2][4], bf[8][2];
                #pragma unroll
                for (int mt = 0; mt < 2; ++mt) {
                    const uint32_t off = (warp*32 + mt*16 + a_row) * 128 + kk * 32 + a_byte;
                    ldmat4(ap[mt], sb + AH_PH + SWZ128(off));
                }
                #pragma unroll
                for (int np = 0; np < 4; ++np) {
                    const uint32_t off = (np*16 + b_row) * 128 + kk * 32 + b_byte;
                    uint32_t r[4];
                    ldmat4(r, sb + AH_VT + SWZ128(off));
                    bf[np*2][0]   = r[0]; bf[np*2][1]   = r[1];
                    bf[np*2+1][0] = r[2]; bf[np*2+1][1] = r[3];
                }
                #pragma unroll
                for (int mt = 0; mt < 2; ++mt)
                    #pragma unroll
                    for (int nt = 0; nt < 8; ++nt)
                        mma_f16(oa[mt][nt], ap[mt], bf[nt]);
            }
        }
    }

    // ---- normalize (lane-local l) + write g_a as HALF ----
    const int b = bh >> 4, h = bh & 15;
    #pragma unroll
    for (int mt = 0; mt < 2; ++mt) {
        const int r0 = warp*32 + mt*16 + g;
        const float i0 = 1.f / fmaxf(lrow[mt][0], 1e-30f);
        const float i1 = 1.f / fmaxf(lrow[mt][1], 1e-30f);
        __half* o0 = g_a + ((size_t)(b * SEQ + q0 + r0)) * DEMB + h * DH;
        __half* o1 = g_a + ((size_t)(b * SEQ + q0 + r0 + 8)) * DEMB + h * DH;
        #pragma unroll
        for (int nt = 0; nt < 8; ++nt) {
            *(__half2*)(o0 + nt*8 + 2*qh) =
                __floats2half2_rn(oa[mt][nt][0] * i0, oa[mt][nt][1] * i0);
            *(__half2*)(o1 + nt*8 + 2*qh) =
                __floats2half2_rn(oa[mt][nt][2] * i1, oa[mt][nt][3] * i1);
        }
    }
}

// ---------------------------------------------------------------------------
extern "C" void kernel_launch(void* const* d_in, const int* in_sizes, int n_in,
                              void* d_out, int out_size)
{
    const float* x     = (const float*)d_in[0];
    const float* w_in  = (const float*)d_in[1];
    const float* b_in  = (const float*)d_in[2];
    const float* w_out = (const float*)d_in[3];
    const float* b_out = (const float*)d_in[4];
    const int*   cmask = (const int*)d_in[5];
    float* out = (float*)d_out;

    cudaFuncSetAttribute(gemm_h<1>, cudaFuncAttributeMaxDynamicSharedMemorySize, SM_TOTAL);
    cudaFuncSetAttribute(gemm_h<2>, cudaFuncAttributeMaxDynamicSharedMemorySize, SM_TOTAL);
    cudaFuncSetAttribute(attn_h,    cudaFuncAttributeMaxDynamicSharedMemorySize, AH_TOTAL);

    round_all<<<(NALL4 + 255) / 256, 256>>>(x, w_in, w_out);

    gemm_h<1><<<dim3(QKV_N/NT, NTOK/MT), 256, SM_TOTAL>>>(
        b_in, nullptr, NTOK, QKV_N, DEMB);

    attn_h<<<dim3(BATCH*NH, SEQ/AQ), 128, AH_TOTAL>>>(cmask);

    gemm_h<2><<<dim3(DEMB/NT, NTOK/MT), 256, SM_TOTAL>>>(
        b_out, out, NTOK, DEMB, DEMB);
}